// round 14
// baseline (speedup 1.0000x reference)
#include <cuda_runtime.h>
#include <cstdint>

// Problem constants
#define NN 64
#define CC 256
#define GG 4
#define HS 16
#define WW 44
#define KK 16
#define NPOS 704              // HS*WW
#define NPOS4 176             // NPOS/4
#define TOPK 88               // int(704*0.125)
#define GATE 0.05f
#define EPSV 1e-6f
#define CH_STRIDE 2816        // GG*NPOS, channel stride in floats
#define TILE_STRIDE 10        // words per position in pooling tile (conflict-free LDS64)

// global scratch for pw: [n][g][k][p]
__device__ float g_pw[NN * GG * KK * NPOS];

// ---------- packed f32x2 helpers ----------
__device__ __forceinline__ unsigned long long pk2(float a, float b) {
    unsigned long long r;
    asm("mov.b64 %0, {%1, %2};" : "=l"(r) : "f"(a), "f"(b));
    return r;
}
__device__ __forceinline__ void ffma2(unsigned long long& d, unsigned long long a, unsigned long long b) {
    asm("fma.rn.f32x2 %0, %1, %2, %0;" : "+l"(d) : "l"(a), "l"(b));
}
__device__ __forceinline__ void add2(unsigned long long& d, unsigned long long a) {
    asm("add.rn.f32x2 %0, %0, %1;" : "+l"(d) : "l"(a));
}
__device__ __forceinline__ unsigned long long mul2(unsigned long long a, unsigned long long b) {
    unsigned long long r;
    asm("mul.rn.f32x2 %0, %1, %2;" : "=l"(r) : "l"(a), "l"(b));
    return r;
}
__device__ __forceinline__ float2 upk2(unsigned long long v) {
    float2 r;
    asm("mov.b64 {%0, %1}, %2;" : "=f"(r.x), "=f"(r.y) : "l"(v));
    return r;
}

__device__ __forceinline__ float warp_sum(float v) {
#pragma unroll
    for (int o = 16; o; o >>= 1) v += __shfl_xor_sync(0xffffffffu, v, o);
    return v;
}
__device__ __forceinline__ float warp_max(float v) {
#pragma unroll
    for (int o = 16; o; o >>= 1) v = fmaxf(v, __shfl_xor_sync(0xffffffffu, v, o));
    return v;
}

// =====================================================================
// Kernel 1: routing. CTA = (g, n), 704 threads, thread = position p.
// 8 channels (4 pairs) per barrier phase. Horizontal pool via shfl on
// register values (edge lanes patch via L1 LDG); vertical via smem tile
// holding hsum. Same 2-barrier structure as the measured-180us loop.
// =====================================================================
__global__ void __launch_bounds__(NPOS, 2) k_route(const float* __restrict__ x,
                                                   const float* __restrict__ lb,
                                                   float* __restrict__ pres_out) {
    const int g = blockIdx.x, n = blockIdx.y;
    const int tid = threadIdx.x;
    const int lane = tid & 31, wid = tid >> 5;

    __shared__ __align__(16) float smem_pool[KK * NPOS];  // 45056 B
    __shared__ float red_s[32];
    __shared__ float colsum_s[KK];
    __shared__ float pinv_s[KK];
    __shared__ float s_emax, s_cnt;

    float* lbn_s = smem_pool;            // [c][k] : 4096 floats
    float* tile  = smem_pool + 4096;     // [p][TILE_STRIDE] : 7040 floats

    // ---- normalize latent basis rows for this g into lbn_s[c*16+k] ----
    if (wid < KK) {
        const float* row = lb + (size_t)(g * KK + wid) * CC;
        float v[8];
        float ss = 0.f;
#pragma unroll
        for (int i = 0; i < 8; i++) { v[i] = row[lane + 32 * i]; ss = fmaf(v[i], v[i], ss); }
        ss = warp_sum(ss);
        float inv = 1.f / fmaxf(sqrtf(ss), 1e-12f);
#pragma unroll
        for (int i = 0; i < 8; i++) lbn_s[(lane + 32 * i) * KK + wid] = v[i] * inv;
    }

    const int p = tid;
    const int ph = p / WW;
    const int pwc = p - ph * WW;
    const float* xbase = x + (size_t)n * CC * CH_STRIDE + (size_t)g * NPOS + p;

    unsigned long long energy2 = 0ULL, n22 = 0ULL;
    unsigned long long dot2[8];
#pragma unroll
    for (int j = 0; j < 8; j++) dot2[j] = 0ULL;

    const bool hasL = (pwc > 0), hasR = (pwc < WW - 1);
    const bool hasU = (ph > 0),  hasD = (ph < HS - 1);
    float* mybase = tile + p * TILE_STRIDE;

    // prefetch batch 0 (4 channel-pairs)
    float2 v[4];
#pragma unroll
    for (int j = 0; j < 4; j++) {
        v[j].x = xbase[(size_t)(2 * j)     * CH_STRIDE];
        v[j].y = xbase[(size_t)(2 * j + 1) * CH_STRIDE];
    }

    for (int b = 0; b < CC / 8; b++) {
        // ---- horizontal sums from registers via shfl (no smem) ----
        unsigned long long hreg[4];
#pragma unroll
        for (int j = 0; j < 4; j++) {
            float upx = __shfl_up_sync(0xffffffffu, v[j].x, 1);
            float upy = __shfl_up_sync(0xffffffffu, v[j].y, 1);
            float dnx = __shfl_down_sync(0xffffffffu, v[j].x, 1);
            float dny = __shfl_down_sync(0xffffffffu, v[j].y, 1);
            if (lane == 0 && hasL) {
                const float* chp = xbase + (size_t)(b * 8 + 2 * j) * CH_STRIDE;
                upx = chp[-1];
                upy = chp[CH_STRIDE - 1];
            }
            if (lane == 31 && hasR) {
                const float* chp = xbase + (size_t)(b * 8 + 2 * j) * CH_STRIDE;
                dnx = chp[1];
                dny = chp[CH_STRIDE + 1];
            }
            float hx = v[j].x, hy = v[j].y;
            if (hasL) { hx += upx; hy += upy; }
            if (hasR) { hx += dnx; hy += dny; }
            hreg[j] = pk2(hx, hy);
            // energy uses center values (still in regs here)
            unsigned long long cen = pk2(v[j].x, v[j].y);
            ffma2(energy2, cen, cen);
        }

        __syncthreads();   // previous batch's vertical tile reads complete
#pragma unroll
        for (int j = 0; j < 4; j++)
            *(unsigned long long*)(mybase + 2 * j) = hreg[j];
        __syncthreads();   // hsum tile visible

        // prefetch next batch (v regs dead -> reuse; 8-deep MLP)
        if (b < CC / 8 - 1) {
            const float* nb = xbase + (size_t)(b + 1) * 8 * CH_STRIDE;
#pragma unroll
            for (int j = 0; j < 4; j++) {
                v[j].x = nb[(size_t)(2 * j)     * CH_STRIDE];
                v[j].y = nb[(size_t)(2 * j + 1) * CH_STRIDE];
            }
        }

        // ---- vertical pass + pooled + dots ----
#pragma unroll
        for (int j = 0; j < 4; j++) {
            const int off = 2 * j;
            unsigned long long s = *(const unsigned long long*)(mybase + off);
            if (hasU) add2(s, *(const unsigned long long*)(mybase - WW * TILE_STRIDE + off));
            if (hasD) add2(s, *(const unsigned long long*)(mybase + WW * TILE_STRIDE + off));
            unsigned long long ninth = pk2(1.f / 9.f, 1.f / 9.f);
            unsigned long long pooled2 = mul2(s, ninth);

            ffma2(n22, pooled2, pooled2);

            float2 pf = upk2(pooled2);
            unsigned long long pa = pk2(pf.x, pf.x);
            unsigned long long pb = pk2(pf.y, pf.y);
            const int c0 = b * 8 + 2 * j;
            const ulonglong2* l0 = (const ulonglong2*)(lbn_s + c0 * KK);
            // channel c0
            {
                ulonglong2 q0 = l0[0], q1 = l0[1], q2 = l0[2], q3 = l0[3];
                ffma2(dot2[0], pa, q0.x); ffma2(dot2[1], pa, q0.y);
                ffma2(dot2[2], pa, q1.x); ffma2(dot2[3], pa, q1.y);
                ffma2(dot2[4], pa, q2.x); ffma2(dot2[5], pa, q2.y);
                ffma2(dot2[6], pa, q3.x); ffma2(dot2[7], pa, q3.y);
            }
            // channel c0+1
            {
                ulonglong2 q0 = l0[4], q1 = l0[5], q2 = l0[6], q3 = l0[7];
                ffma2(dot2[0], pb, q0.x); ffma2(dot2[1], pb, q0.y);
                ffma2(dot2[2], pb, q1.x); ffma2(dot2[3], pb, q1.y);
                ffma2(dot2[4], pb, q2.x); ffma2(dot2[5], pb, q2.y);
                ffma2(dot2[6], pb, q3.x); ffma2(dot2[7], pb, q3.y);
            }
        }
    }

    float2 et = upk2(energy2);
    float energy = et.x + et.y;
    float2 nt = upk2(n22);
    float n2 = nt.x + nt.y;

    __syncthreads();

    // ---- energy max over block ----
    float wm = warp_max(energy);
    if (lane == 0) red_s[wid] = wm;
    __syncthreads();
    if (tid == 0) {
        float m = red_s[0];
        for (int w = 1; w < 22; w++) m = fmaxf(m, red_s[w]);
        s_emax = m;
    }
    __syncthreads();

    float denom = fmaxf(s_emax * (1.f / 256.f), EPSV);
    float en = (energy * (1.f / 256.f)) / denom;
    bool amb = en > GATE;

    float cw = warp_sum(amb ? 1.f : 0.f);
    if (lane == 0) red_s[wid] = cw;
    __syncthreads();
    if (tid == 0) {
        float m = 0.f;
        for (int w = 0; w < 22; w++) m += red_s[w];
        s_cnt = m;
    }
    __syncthreads();
    if (s_cnt <= 0.f) amb = (energy > 0.f);
    float am_f = amb ? 1.f : 0.f;

    // ---- logits -> softmax -> supp (registers) ----
    float d[KK];
#pragma unroll
    for (int j = 0; j < 8; j++) {
        float2 t = upk2(dot2[j]);
        d[2 * j] = t.x;
        d[2 * j + 1] = t.y;
    }
    float inv = 1.f / fmaxf(sqrtf(n2), 1e-12f);
    float mx = -1e30f;
#pragma unroll
    for (int k = 0; k < KK; k++) { d[k] = d[k] * inv * 8.f; mx = fmaxf(mx, d[k]); }
    float se = 0.f;
#pragma unroll
    for (int k = 0; k < KK; k++) { d[k] = __expf(d[k] - mx); se += d[k]; }
    float sc = am_f / se;   // supp[k] = d[k]*sc

    float* supp_s = smem_pool;   // reuse (lbn/tile done)
#pragma unroll
    for (int k = 0; k < KK; k++) supp_s[k * NPOS + p] = d[k] * sc;
    __syncthreads();

    // ---- per-k: colsum + exact top-88 presence (warp k owns column k) ----
    if (wid < KK) {
        float vals[22];
        float s = 0.f;
#pragma unroll
        for (int i = 0; i < 22; i++) {
            vals[i] = supp_s[wid * NPOS + lane + 32 * i];
            s += vals[i];
        }
        s = warp_sum(s);
        if (lane == 0) colsum_s[wid] = s;

        // binary search on nonneg float bit patterns for 88th largest
        unsigned V = 0u;
        for (int bit = 30; bit >= 0; --bit) {
            unsigned cand = V | (1u << bit);
            float cf = __uint_as_float(cand);
            int cnt = 0;
#pragma unroll
            for (int i = 0; i < 22; i++) cnt += (vals[i] >= cf) ? 1 : 0;
            cnt = __reduce_add_sync(0xffffffffu, cnt);
            if (cnt >= TOPK) V = cand;
        }
        float kth = __uint_as_float(V);
        int cgt = 0;
        float sgt = 0.f;
#pragma unroll
        for (int i = 0; i < 22; i++) {
            if (vals[i] > kth) { cgt++; sgt += vals[i]; }
        }
        cgt = __reduce_add_sync(0xffffffffu, cgt);
        sgt = warp_sum(sgt);
        if (lane == 0) {
            float pr = (sgt + kth * (float)(TOPK - cgt)) * (1.f / (float)TOPK);
            pres_out[n * (GG * KK) + g * KK + wid] = pr;
        }
    }
    __syncthreads();
    if (tid < KK) pinv_s[tid] = 1.f / fmaxf(colsum_s[tid], EPSV);
    __syncthreads();

    // ---- pw = supp / colsum -> global scratch ----
    float* gpw = g_pw + (size_t)(n * GG + g) * KK * NPOS;
#pragma unroll
    for (int k = 0; k < KK; k++) gpw[k * NPOS + p] = d[k] * sc * pinv_s[k];
}

// =====================================================================
// Kernel 2: tokens[k][c] = sum_p pw[p][k] * x[c][p].  CTA = (g, n),
// 128 threads, thread = channels (c, c+128).
// x staged through a padded smem tile per 16-position chunk (coalesced
// LDG, per-octet conflict-free LDS); pw resident in smem, warp-uniform
// broadcast LDS128. 64KB dynamic smem -> 3 CTAs/SM.
// g==0 CTA also normalizes its batch's presence row at the end.
// =====================================================================
#define PCH 16               // positions per chunk
#define NCHUNK 44            // 704/16
#define XS_STRIDE 20         // floats per channel row in x_s (4 float4 + pad)
#define XS_FLOATS (CC * XS_STRIDE)              // 5120 floats = 20480 B
#define TOK_SMEM ((XS_FLOATS + KK * NPOS) * 4)  // 20480 + 45056 = 65536 B

__global__ void __launch_bounds__(128) k_tokens(const float* __restrict__ x,
                                                float* __restrict__ out,
                                                float* __restrict__ pres) {
    extern __shared__ __align__(16) float dsm[];
    float* x_s  = dsm;                 // [256][20]
    float* pw_s = dsm + XS_FLOATS;     // [16][704]

    const int g = blockIdx.x, n = blockIdx.y;
    const int tid = threadIdx.x;

    // load pw into smem once (coalesced; first loop barrier orders it)
    {
        const float4* src = (const float4*)(g_pw + (size_t)(n * GG + g) * KK * NPOS);
        float4* dst = (float4*)pw_s;
#pragma unroll
        for (int i = 0; i < 22; i++) dst[tid + 128 * i] = src[tid + 128 * i];
    }

    const float* xg = x + (size_t)n * CC * CH_STRIDE + (size_t)g * NPOS;
    const int c0 = tid;
    const int c1 = tid + 128;

    unsigned long long accA[KK], accB[KK];
#pragma unroll
    for (int k = 0; k < KK; k++) { accA[k] = 0ULL; accB[k] = 0ULL; }

    for (int ch = 0; ch < NCHUNK; ch++) {
        const int p0 = ch * PCH;
        __syncthreads();   // prior chunk x_s reads done (and pw_s ready on ch=0)
        // stage 256 channels x 16 positions, coalesced LDG -> padded smem
#pragma unroll
        for (int it = 0; it < 8; it++) {
            int f = tid + 128 * it;          // 0..1023
            int c = f >> 2, i = f & 3;
            float4 vv = __ldg((const float4*)(xg + (size_t)c * CH_STRIDE + p0) + i);
            *(float4*)(x_s + c * XS_STRIDE + i * 4) = vv;
        }
        __syncthreads();

        const int p4base = ch * (PCH / 4);
#pragma unroll
        for (int i = 0; i < 4; i++) {
            float4 xa = *(const float4*)(x_s + c0 * XS_STRIDE + i * 4);
            float4 xb = *(const float4*)(x_s + c1 * XS_STRIDE + i * 4);
            unsigned long long alo = pk2(xa.x, xa.y);
            unsigned long long ahi = pk2(xa.z, xa.w);
            unsigned long long blo = pk2(xb.x, xb.y);
            unsigned long long bhi = pk2(xb.z, xb.w);
            const float* pwrow = pw_s + 4 * (p4base + i);
#pragma unroll
            for (int k = 0; k < KK; k++) {
                ulonglong2 pv = *(const ulonglong2*)(pwrow + k * NPOS);  // broadcast
                ffma2(accA[k], alo, pv.x);
                ffma2(accA[k], ahi, pv.y);
                ffma2(accB[k], blo, pv.x);
                ffma2(accB[k], bhi, pv.y);
            }
        }
    }

    float resA[KK], resB[KK];
#pragma unroll
    for (int k = 0; k < KK; k++) {
        float2 ta = upk2(accA[k]);
        resA[k] = ta.x + ta.y;
        float2 tb = upk2(accB[k]);
        resB[k] = tb.x + tb.y;
    }
    float4* oa = (float4*)(out + (size_t)(n * CC + c0) * (GG * KK) + g * KK);
    oa[0] = make_float4(resA[0], resA[1], resA[2], resA[3]);
    oa[1] = make_float4(resA[4], resA[5], resA[6], resA[7]);
    oa[2] = make_float4(resA[8], resA[9], resA[10], resA[11]);
    oa[3] = make_float4(resA[12], resA[13], resA[14], resA[15]);
    float4* ob = (float4*)(out + (size_t)(n * CC + c1) * (GG * KK) + g * KK);
    ob[0] = make_float4(resB[0], resB[1], resB[2], resB[3]);
    ob[1] = make_float4(resB[4], resB[5], resB[6], resB[7]);
    ob[2] = make_float4(resB[8], resB[9], resB[10], resB[11]);
    ob[3] = make_float4(resB[12], resB[13], resB[14], resB[15]);

    // ---- g==0 CTA: normalize presence row n in place ----
    if (g == 0) {
        float pv = 0.f;
        if (tid < 64) pv = pres[n * 64 + tid];
        float ws = warp_sum(pv);
        if ((tid & 31) == 0) x_s[tid >> 5] = ws;   // warps 0..3 write slots 0..3
        __syncthreads();
        if (tid < 64) {
            float tot = x_s[0] + x_s[1];
            pres[n * 64 + tid] = pv / fmaxf(tot, EPSV);
        }
    }
}

extern "C" void kernel_launch(void* const* d_in, const int* in_sizes, int n_in,
                              void* d_out, int out_size) {
    const float* x = (const float*)d_in[0];
    const float* lb = (const float*)d_in[1];
    float* out = (float*)d_out;
    float* pres = out + (size_t)NN * CC * (GG * KK);   // tokens first, then pres

    static int smem_set = 0;
    if (!smem_set) {
        cudaFuncSetAttribute(k_tokens, cudaFuncAttributeMaxDynamicSharedMemorySize, TOK_SMEM);
        smem_set = 1;
    }

    dim3 grid(GG, NN);
    k_route<<<grid, NPOS>>>(x, lb, pres);
    k_tokens<<<grid, 128, TOK_SMEM>>>(x, out, pres);
}

// round 15
// speedup vs baseline: 1.0153x; 1.0153x over previous
#include <cuda_runtime.h>
#include <cstdint>

// Problem constants
#define NN 64
#define CC 256
#define GG 4
#define HS 16
#define WW 44
#define KK 16
#define NPOS 704              // HS*WW
#define NPOS4 176             // NPOS/4
#define TOPK 88               // int(704*0.125)
#define GATE 0.05f
#define EPSV 1e-6f
#define CH_STRIDE 2816        // GG*NPOS, channel stride in floats
#define TILE_STRIDE 10        // words per position in pooling tile

#define TOK_N (NN * CC * GG * KK)   // tokens element count = 1048576

// global scratch: pw [n][g][k][p], token partials [2][n][c][g*16+k]
__device__ float g_pw[NN * GG * KK * NPOS];
__device__ float g_tok[2 * TOK_N];

// ---------- packed f32x2 helpers ----------
__device__ __forceinline__ unsigned long long pk2(float a, float b) {
    unsigned long long r;
    asm("mov.b64 %0, {%1, %2};" : "=l"(r) : "f"(a), "f"(b));
    return r;
}
__device__ __forceinline__ void ffma2(unsigned long long& d, unsigned long long a, unsigned long long b) {
    asm("fma.rn.f32x2 %0, %1, %2, %0;" : "+l"(d) : "l"(a), "l"(b));
}
__device__ __forceinline__ void add2(unsigned long long& d, unsigned long long a) {
    asm("add.rn.f32x2 %0, %0, %1;" : "+l"(d) : "l"(a));
}
__device__ __forceinline__ unsigned long long mul2(unsigned long long a, unsigned long long b) {
    unsigned long long r;
    asm("mul.rn.f32x2 %0, %1, %2;" : "=l"(r) : "l"(a), "l"(b));
    return r;
}
__device__ __forceinline__ float2 upk2(unsigned long long v) {
    float2 r;
    asm("mov.b64 {%0, %1}, %2;" : "=f"(r.x), "=f"(r.y) : "l"(v));
    return r;
}

__device__ __forceinline__ float warp_sum(float v) {
#pragma unroll
    for (int o = 16; o; o >>= 1) v += __shfl_xor_sync(0xffffffffu, v, o);
    return v;
}
__device__ __forceinline__ float warp_max(float v) {
#pragma unroll
    for (int o = 16; o; o >>= 1) v = fmaxf(v, __shfl_xor_sync(0xffffffffu, v, o));
    return v;
}

// =====================================================================
// Kernel 1: routing. CTA = (g, n), 704 threads, thread = position p.
// 8 channels (4 pairs) per barrier phase. Horizontal pool via shfl on
// register values (edge lanes patch via L1 LDG); vertical via smem tile
// holding hsum. (R14 structure — measured ~177us.)
// =====================================================================
__global__ void __launch_bounds__(NPOS, 2) k_route(const float* __restrict__ x,
                                                   const float* __restrict__ lb,
                                                   float* __restrict__ pres_out) {
    const int g = blockIdx.x, n = blockIdx.y;
    const int tid = threadIdx.x;
    const int lane = tid & 31, wid = tid >> 5;

    __shared__ __align__(16) float smem_pool[KK * NPOS];  // 45056 B
    __shared__ float red_s[32];
    __shared__ float colsum_s[KK];
    __shared__ float pinv_s[KK];
    __shared__ float s_emax, s_cnt;

    float* lbn_s = smem_pool;            // [c][k] : 4096 floats
    float* tile  = smem_pool + 4096;     // [p][TILE_STRIDE] : 7040 floats

    // ---- normalize latent basis rows for this g into lbn_s[c*16+k] ----
    if (wid < KK) {
        const float* row = lb + (size_t)(g * KK + wid) * CC;
        float v[8];
        float ss = 0.f;
#pragma unroll
        for (int i = 0; i < 8; i++) { v[i] = row[lane + 32 * i]; ss = fmaf(v[i], v[i], ss); }
        ss = warp_sum(ss);
        float inv = 1.f / fmaxf(sqrtf(ss), 1e-12f);
#pragma unroll
        for (int i = 0; i < 8; i++) lbn_s[(lane + 32 * i) * KK + wid] = v[i] * inv;
    }

    const int p = tid;
    const int ph = p / WW;
    const int pwc = p - ph * WW;
    const float* xbase = x + (size_t)n * CC * CH_STRIDE + (size_t)g * NPOS + p;

    unsigned long long energy2 = 0ULL, n22 = 0ULL;
    unsigned long long dot2[8];
#pragma unroll
    for (int j = 0; j < 8; j++) dot2[j] = 0ULL;

    const bool hasL = (pwc > 0), hasR = (pwc < WW - 1);
    const bool hasU = (ph > 0),  hasD = (ph < HS - 1);
    float* mybase = tile + p * TILE_STRIDE;

    // prefetch batch 0 (4 channel-pairs)
    float2 v[4];
#pragma unroll
    for (int j = 0; j < 4; j++) {
        v[j].x = xbase[(size_t)(2 * j)     * CH_STRIDE];
        v[j].y = xbase[(size_t)(2 * j + 1) * CH_STRIDE];
    }

    for (int b = 0; b < CC / 8; b++) {
        // ---- horizontal sums from registers via shfl (no smem) ----
        unsigned long long hreg[4];
#pragma unroll
        for (int j = 0; j < 4; j++) {
            float upx = __shfl_up_sync(0xffffffffu, v[j].x, 1);
            float upy = __shfl_up_sync(0xffffffffu, v[j].y, 1);
            float dnx = __shfl_down_sync(0xffffffffu, v[j].x, 1);
            float dny = __shfl_down_sync(0xffffffffu, v[j].y, 1);
            if (lane == 0 && hasL) {
                const float* chp = xbase + (size_t)(b * 8 + 2 * j) * CH_STRIDE;
                upx = chp[-1];
                upy = chp[CH_STRIDE - 1];
            }
            if (lane == 31 && hasR) {
                const float* chp = xbase + (size_t)(b * 8 + 2 * j) * CH_STRIDE;
                dnx = chp[1];
                dny = chp[CH_STRIDE + 1];
            }
            float hx = v[j].x, hy = v[j].y;
            if (hasL) { hx += upx; hy += upy; }
            if (hasR) { hx += dnx; hy += dny; }
            hreg[j] = pk2(hx, hy);
            // energy uses center values (still in regs here)
            unsigned long long cen = pk2(v[j].x, v[j].y);
            ffma2(energy2, cen, cen);
        }

        __syncthreads();   // previous batch's vertical tile reads complete
#pragma unroll
        for (int j = 0; j < 4; j++)
            *(unsigned long long*)(mybase + 2 * j) = hreg[j];
        __syncthreads();   // hsum tile visible

        // prefetch next batch (v regs dead -> reuse; 8-deep MLP)
        if (b < CC / 8 - 1) {
            const float* nb = xbase + (size_t)(b + 1) * 8 * CH_STRIDE;
#pragma unroll
            for (int j = 0; j < 4; j++) {
                v[j].x = nb[(size_t)(2 * j)     * CH_STRIDE];
                v[j].y = nb[(size_t)(2 * j + 1) * CH_STRIDE];
            }
        }

        // ---- vertical pass + pooled + dots ----
#pragma unroll
        for (int j = 0; j < 4; j++) {
            const int off = 2 * j;
            unsigned long long s = *(const unsigned long long*)(mybase + off);
            if (hasU) add2(s, *(const unsigned long long*)(mybase - WW * TILE_STRIDE + off));
            if (hasD) add2(s, *(const unsigned long long*)(mybase + WW * TILE_STRIDE + off));
            unsigned long long ninth = pk2(1.f / 9.f, 1.f / 9.f);
            unsigned long long pooled2 = mul2(s, ninth);

            ffma2(n22, pooled2, pooled2);

            float2 pf = upk2(pooled2);
            unsigned long long pa = pk2(pf.x, pf.x);
            unsigned long long pb = pk2(pf.y, pf.y);
            const int c0 = b * 8 + 2 * j;
            const ulonglong2* l0 = (const ulonglong2*)(lbn_s + c0 * KK);
            // channel c0
            {
                ulonglong2 q0 = l0[0], q1 = l0[1], q2 = l0[2], q3 = l0[3];
                ffma2(dot2[0], pa, q0.x); ffma2(dot2[1], pa, q0.y);
                ffma2(dot2[2], pa, q1.x); ffma2(dot2[3], pa, q1.y);
                ffma2(dot2[4], pa, q2.x); ffma2(dot2[5], pa, q2.y);
                ffma2(dot2[6], pa, q3.x); ffma2(dot2[7], pa, q3.y);
            }
            // channel c0+1
            {
                ulonglong2 q0 = l0[4], q1 = l0[5], q2 = l0[6], q3 = l0[7];
                ffma2(dot2[0], pb, q0.x); ffma2(dot2[1], pb, q0.y);
                ffma2(dot2[2], pb, q1.x); ffma2(dot2[3], pb, q1.y);
                ffma2(dot2[4], pb, q2.x); ffma2(dot2[5], pb, q2.y);
                ffma2(dot2[6], pb, q3.x); ffma2(dot2[7], pb, q3.y);
            }
        }
    }

    float2 et = upk2(energy2);
    float energy = et.x + et.y;
    float2 nt = upk2(n22);
    float n2 = nt.x + nt.y;

    __syncthreads();

    // ---- energy max over block ----
    float wm = warp_max(energy);
    if (lane == 0) red_s[wid] = wm;
    __syncthreads();
    if (tid == 0) {
        float m = red_s[0];
        for (int w = 1; w < 22; w++) m = fmaxf(m, red_s[w]);
        s_emax = m;
    }
    __syncthreads();

    float denom = fmaxf(s_emax * (1.f / 256.f), EPSV);
    float en = (energy * (1.f / 256.f)) / denom;
    bool amb = en > GATE;

    float cw = warp_sum(amb ? 1.f : 0.f);
    if (lane == 0) red_s[wid] = cw;
    __syncthreads();
    if (tid == 0) {
        float m = 0.f;
        for (int w = 0; w < 22; w++) m += red_s[w];
        s_cnt = m;
    }
    __syncthreads();
    if (s_cnt <= 0.f) amb = (energy > 0.f);
    float am_f = amb ? 1.f : 0.f;

    // ---- logits -> softmax -> supp (registers) ----
    float d[KK];
#pragma unroll
    for (int j = 0; j < 8; j++) {
        float2 t = upk2(dot2[j]);
        d[2 * j] = t.x;
        d[2 * j + 1] = t.y;
    }
    float inv = 1.f / fmaxf(sqrtf(n2), 1e-12f);
    float mx = -1e30f;
#pragma unroll
    for (int k = 0; k < KK; k++) { d[k] = d[k] * inv * 8.f; mx = fmaxf(mx, d[k]); }
    float se = 0.f;
#pragma unroll
    for (int k = 0; k < KK; k++) { d[k] = __expf(d[k] - mx); se += d[k]; }
    float sc = am_f / se;   // supp[k] = d[k]*sc

    float* supp_s = smem_pool;   // reuse (lbn/tile done)
#pragma unroll
    for (int k = 0; k < KK; k++) supp_s[k * NPOS + p] = d[k] * sc;
    __syncthreads();

    // ---- per-k: colsum + exact top-88 presence (warp k owns column k) ----
    if (wid < KK) {
        float vals[22];
        float s = 0.f;
#pragma unroll
        for (int i = 0; i < 22; i++) {
            vals[i] = supp_s[wid * NPOS + lane + 32 * i];
            s += vals[i];
        }
        s = warp_sum(s);
        if (lane == 0) colsum_s[wid] = s;

        // binary search on nonneg float bit patterns for 88th largest
        unsigned V = 0u;
        for (int bit = 30; bit >= 0; --bit) {
            unsigned cand = V | (1u << bit);
            float cf = __uint_as_float(cand);
            int cnt = 0;
#pragma unroll
            for (int i = 0; i < 22; i++) cnt += (vals[i] >= cf) ? 1 : 0;
            cnt = __reduce_add_sync(0xffffffffu, cnt);
            if (cnt >= TOPK) V = cand;
        }
        float kth = __uint_as_float(V);
        int cgt = 0;
        float sgt = 0.f;
#pragma unroll
        for (int i = 0; i < 22; i++) {
            if (vals[i] > kth) { cgt++; sgt += vals[i]; }
        }
        cgt = __reduce_add_sync(0xffffffffu, cgt);
        sgt = warp_sum(sgt);
        if (lane == 0) {
            float pr = (sgt + kth * (float)(TOPK - cgt)) * (1.f / (float)TOPK);
            pres_out[n * (GG * KK) + g * KK + wid] = pr;
        }
    }
    __syncthreads();
    if (tid < KK) pinv_s[tid] = 1.f / fmaxf(colsum_s[tid], EPSV);
    __syncthreads();

    // ---- pw = supp / colsum -> global scratch ----
    float* gpw = g_pw + (size_t)(n * GG + g) * KK * NPOS;
#pragma unroll
    for (int k = 0; k < KK; k++) gpw[k * NPOS + p] = d[k] * sc * pinv_s[k];
}

// =====================================================================
// Kernel 2: partial tokens. CTA = (g, n, s); s splits positions in two
// 352-position halves. 128 threads, thread = channels (c, c+128).
// x staged through padded smem per 32-position chunk (coalesced LDG,
// conflict-free LDS); half-pw resident in smem (broadcast LDS128).
// 59.4KB dynamic smem -> 3 CTAs/SM, grid 512 -> ~1.15 waves.
// =====================================================================
#define NSPLIT 2
#define NPOS_H (NPOS / NSPLIT)        // 352
#define NPOS_H4 (NPOS_H / 4)          // 88
#define PCH 32                        // positions per chunk
#define NCHUNK_H (NPOS_H / PCH)       // 11
#define XS_STRIDE 36                  // floats per channel row (8 float4 + pad)
#define XS_FLOATS (CC * XS_STRIDE)    // 9216 floats = 36864 B
#define TOK_SMEM ((XS_FLOATS + KK * NPOS_H) * 4)   // 36864 + 22528 = 59392 B

__global__ void __launch_bounds__(128) k_tokens(const float* __restrict__ x) {
    extern __shared__ __align__(16) float dsm[];
    float* x_s  = dsm;                 // [256][36]
    float* pw_s = dsm + XS_FLOATS;     // [16][352]

    const int g = blockIdx.x, n = blockIdx.y, s = blockIdx.z;
    const int tid = threadIdx.x;
    const int pbase = s * NPOS_H;

    // load half-pw into smem (coalesced; first loop barrier orders it)
    {
        const float4* src = (const float4*)(g_pw + (size_t)(n * GG + g) * KK * NPOS);
        float4* dst = (float4*)pw_s;
#pragma unroll
        for (int it = 0; it < 11; it++) {
            int t = tid + 128 * it;          // 0..1407
            int k = t / NPOS_H4, j = t - k * NPOS_H4;
            dst[t] = src[k * NPOS4 + s * NPOS_H4 + j];
        }
    }

    const float* xg = x + (size_t)n * CC * CH_STRIDE + (size_t)g * NPOS + pbase;
    const int c0 = tid;
    const int c1 = tid + 128;

    unsigned long long accA[KK], accB[KK];
#pragma unroll
    for (int k = 0; k < KK; k++) { accA[k] = 0ULL; accB[k] = 0ULL; }

    for (int ch = 0; ch < NCHUNK_H; ch++) {
        const int p0 = ch * PCH;
        __syncthreads();   // prior chunk x_s reads done (and pw_s ready on ch=0)
        // stage 256 channels x 32 positions, coalesced LDG -> padded smem
#pragma unroll
        for (int it = 0; it < 16; it++) {
            int f = tid + 128 * it;          // 0..2047
            int c = f >> 3, i = f & 7;
            float4 vv = __ldg((const float4*)(xg + (size_t)c * CH_STRIDE + p0) + i);
            *(float4*)(x_s + c * XS_STRIDE + i * 4) = vv;
        }
        __syncthreads();

        const int p4base = ch * (PCH / 4);
#pragma unroll
        for (int i = 0; i < 8; i++) {
            float4 xa = *(const float4*)(x_s + c0 * XS_STRIDE + i * 4);
            float4 xb = *(const float4*)(x_s + c1 * XS_STRIDE + i * 4);
            unsigned long long alo = pk2(xa.x, xa.y);
            unsigned long long ahi = pk2(xa.z, xa.w);
            unsigned long long blo = pk2(xb.x, xb.y);
            unsigned long long bhi = pk2(xb.z, xb.w);
            const float* pwrow = pw_s + 4 * (p4base + i);
#pragma unroll
            for (int k = 0; k < KK; k++) {
                ulonglong2 pv = *(const ulonglong2*)(pwrow + k * NPOS_H);  // broadcast
                ffma2(accA[k], alo, pv.x);
                ffma2(accA[k], ahi, pv.y);
                ffma2(accB[k], blo, pv.x);
                ffma2(accB[k], bhi, pv.y);
            }
        }
    }

    float resA[KK], resB[KK];
#pragma unroll
    for (int k = 0; k < KK; k++) {
        float2 ta = upk2(accA[k]);
        resA[k] = ta.x + ta.y;
        float2 tb = upk2(accB[k]);
        resB[k] = tb.x + tb.y;
    }
    float* po = g_tok + (size_t)s * TOK_N;
    float4* oa = (float4*)(po + (size_t)(n * CC + c0) * (GG * KK) + g * KK);
    oa[0] = make_float4(resA[0], resA[1], resA[2], resA[3]);
    oa[1] = make_float4(resA[4], resA[5], resA[6], resA[7]);
    oa[2] = make_float4(resA[8], resA[9], resA[10], resA[11]);
    oa[3] = make_float4(resA[12], resA[13], resA[14], resA[15]);
    float4* ob = (float4*)(po + (size_t)(n * CC + c1) * (GG * KK) + g * KK);
    ob[0] = make_float4(resB[0], resB[1], resB[2], resB[3]);
    ob[1] = make_float4(resB[4], resB[5], resB[6], resB[7]);
    ob[2] = make_float4(resB[8], resB[9], resB[10], resB[11]);
    ob[3] = make_float4(resB[12], resB[13], resB[14], resB[15]);
}

// =====================================================================
// Kernel 3: finish. Blocks 0..255 sum the two token partials into out
// (fixed order -> deterministic); blocks 256..319 normalize presence.
// =====================================================================
__global__ void __launch_bounds__(256) k_finish(float* __restrict__ out) {
    const int b = blockIdx.x;
    if (b < 256) {
        const float4* p0 = (const float4*)g_tok;
        const float4* p1 = (const float4*)(g_tok + TOK_N);
        float4* o = (float4*)out;
        const int base = b * 1024 + threadIdx.x;
#pragma unroll
        for (int i = 0; i < 4; i++) {
            int idx = base + 256 * i;
            float4 a = p0[idx], c = p1[idx];
            o[idx] = make_float4(a.x + c.x, a.y + c.y, a.z + c.z, a.w + c.w);
        }
    } else {
        float* pres = out + TOK_N;
        const int n = b - 256;
        const int t = threadIdx.x;
        __shared__ float sh[2];
        float v = 0.f;
        if (t < 64) v = pres[n * 64 + t];
        float ws = warp_sum(v);
        if (t == 0) sh[0] = ws;
        if (t == 32) sh[1] = ws;
        __syncthreads();
        if (t < 64) pres[n * 64 + t] = v / fmaxf(sh[0] + sh[1], EPSV);
    }
}

extern "C" void kernel_launch(void* const* d_in, const int* in_sizes, int n_in,
                              void* d_out, int out_size) {
    const float* x = (const float*)d_in[0];
    const float* lb = (const float*)d_in[1];
    float* out = (float*)d_out;
    float* pres = out + (size_t)TOK_N;   // tokens first, then pres

    static int smem_set = 0;
    if (!smem_set) {
        cudaFuncSetAttribute(k_tokens, cudaFuncAttributeMaxDynamicSharedMemorySize, TOK_SMEM);
        smem_set = 1;
    }

    k_route<<<dim3(GG, NN), NPOS>>>(x, lb, pres);
    k_tokens<<<dim3(GG, NN, NSPLIT), 128, TOK_SMEM>>>(x);
    k_finish<<<320, 256>>>(out);
}

// round 17
// speedup vs baseline: 1.1635x; 1.1460x over previous
#include <cuda_runtime.h>
#include <cstdint>

// Problem constants
#define NN 64
#define CC 256
#define GG 4
#define HS 16
#define WW 44
#define KK 16
#define NPOS 704              // HS*WW
#define NPOS4 176             // NPOS/4
#define TOPK 88               // int(704*0.125)
#define GATE 0.05f
#define EPSV 1e-6f
#define CH_STRIDE 2816        // GG*NPOS, channel stride in floats
#define TILE_STRIDE 10        // words per position in pooling tile

#define THR 352               // k_route threads: 2 positions per thread
#define NWARP 11              // THR/32

#define TOK_N (NN * CC * GG * KK)   // tokens element count = 1048576

// global scratch: pw [n][g][k][p], token partials [2][n][c][g*16+k]
__device__ float g_pw[NN * GG * KK * NPOS];
__device__ float g_tok[2 * TOK_N];

// ---------- packed f32x2 helpers ----------
__device__ __forceinline__ unsigned long long pk2(float a, float b) {
    unsigned long long r;
    asm("mov.b64 %0, {%1, %2};" : "=l"(r) : "f"(a), "f"(b));
    return r;
}
__device__ __forceinline__ void ffma2(unsigned long long& d, unsigned long long a, unsigned long long b) {
    asm("fma.rn.f32x2 %0, %1, %2, %0;" : "+l"(d) : "l"(a), "l"(b));
}
__device__ __forceinline__ void add2(unsigned long long& d, unsigned long long a) {
    asm("add.rn.f32x2 %0, %0, %1;" : "+l"(d) : "l"(a));
}
__device__ __forceinline__ unsigned long long mul2(unsigned long long a, unsigned long long b) {
    unsigned long long r;
    asm("mul.rn.f32x2 %0, %1, %2;" : "=l"(r) : "l"(a), "l"(b));
    return r;
}
__device__ __forceinline__ float2 upk2(unsigned long long v) {
    float2 r;
    asm("mov.b64 {%0, %1}, %2;" : "=f"(r.x), "=f"(r.y) : "l"(v));
    return r;
}

__device__ __forceinline__ float warp_sum(float v) {
#pragma unroll
    for (int o = 16; o; o >>= 1) v += __shfl_xor_sync(0xffffffffu, v, o);
    return v;
}
__device__ __forceinline__ float warp_max(float v) {
#pragma unroll
    for (int o = 16; o; o >>= 1) v = fmaxf(v, __shfl_xor_sync(0xffffffffu, v, o));
    return v;
}

// =====================================================================
// Kernel 1: routing. CTA = (g, n), 352 threads, thread = positions
// (p, p+352). 8 channels per barrier phase; horizontal pool via shfl;
// vertical via smem tile. Each latent LDS128 feeds BOTH positions'
// dots (broadcast wf amortized 2x vs the 704-thread variant).
// =====================================================================
__global__ void __launch_bounds__(THR, 2) k_route(const float* __restrict__ x,
                                                  const float* __restrict__ lb,
                                                  float* __restrict__ pres_out) {
    const int g = blockIdx.x, n = blockIdx.y;
    const int tid = threadIdx.x;
    const int lane = tid & 31, wid = tid >> 5;

    __shared__ __align__(16) float smem_pool[KK * NPOS];  // 45056 B
    __shared__ float red_s[NWARP];
    __shared__ float colsum_s[KK];
    __shared__ float pinv_s[KK];
    __shared__ float s_emax, s_cnt;

    float* lbn_s = smem_pool;            // [c][k] : 4096 floats
    float* tile  = smem_pool + 4096;     // [p][TILE_STRIDE] : 7040 floats

    // ---- normalize latent basis rows for this g into lbn_s[c*16+k] ----
    for (int kk = wid; kk < KK; kk += NWARP) {
        const float* row = lb + (size_t)(g * KK + kk) * CC;
        float v[8];
        float ss = 0.f;
#pragma unroll
        for (int i = 0; i < 8; i++) { v[i] = row[lane + 32 * i]; ss = fmaf(v[i], v[i], ss); }
        ss = warp_sum(ss);
        float inv = 1.f / fmaxf(sqrtf(ss), 1e-12f);
#pragma unroll
        for (int i = 0; i < 8; i++) lbn_s[(lane + 32 * i) * KK + kk] = v[i] * inv;
    }

    const int p0 = tid, p1 = tid + THR;
    const int ph0 = p0 / WW, pwc0 = p0 - ph0 * WW;
    const int ph1 = p1 / WW, pwc1 = p1 - ph1 * WW;
    const float* xb0 = x + (size_t)n * CC * CH_STRIDE + (size_t)g * NPOS + p0;
    const float* xb1 = xb0 + THR;

    const bool L0 = (pwc0 > 0), R0 = (pwc0 < WW - 1), U0 = (ph0 > 0), D0 = (ph0 < HS - 1);
    const bool L1 = (pwc1 > 0), R1 = (pwc1 < WW - 1), U1 = (ph1 > 0), D1 = (ph1 < HS - 1);
    float* mb0 = tile + p0 * TILE_STRIDE;
    float* mb1 = tile + p1 * TILE_STRIDE;

    unsigned long long e2a = 0ULL, e2b = 0ULL, n2a = 0ULL, n2b = 0ULL;
    unsigned long long dotA[8], dotB[8];
#pragma unroll
    for (int j = 0; j < 8; j++) { dotA[j] = 0ULL; dotB[j] = 0ULL; }

    // prefetch batch 0 (4 channel-pairs x 2 positions)
    float2 va[4], vb[4];
#pragma unroll
    for (int j = 0; j < 4; j++) {
        va[j].x = xb0[(size_t)(2 * j)     * CH_STRIDE];
        va[j].y = xb0[(size_t)(2 * j + 1) * CH_STRIDE];
        vb[j].x = xb1[(size_t)(2 * j)     * CH_STRIDE];
        vb[j].y = xb1[(size_t)(2 * j + 1) * CH_STRIDE];
    }

    for (int b = 0; b < CC / 8; b++) {
        // ---- horizontal sums via shfl (edge lanes patch via L1 LDG) ----
        unsigned long long hA[4], hB[4];
#pragma unroll
        for (int j = 0; j < 4; j++) {
            float ux = __shfl_up_sync(0xffffffffu, va[j].x, 1);
            float uy = __shfl_up_sync(0xffffffffu, va[j].y, 1);
            float dx = __shfl_down_sync(0xffffffffu, va[j].x, 1);
            float dy = __shfl_down_sync(0xffffffffu, va[j].y, 1);
            if (lane == 0 && L0) {
                const float* c = xb0 + (size_t)(b * 8 + 2 * j) * CH_STRIDE;
                ux = c[-1]; uy = c[CH_STRIDE - 1];
            }
            if (lane == 31 && R0) {
                const float* c = xb0 + (size_t)(b * 8 + 2 * j) * CH_STRIDE;
                dx = c[1]; dy = c[CH_STRIDE + 1];
            }
            float hx = va[j].x, hy = va[j].y;
            if (L0) { hx += ux; hy += uy; }
            if (R0) { hx += dx; hy += dy; }
            hA[j] = pk2(hx, hy);
            unsigned long long cen = pk2(va[j].x, va[j].y);
            ffma2(e2a, cen, cen);
        }
#pragma unroll
        for (int j = 0; j < 4; j++) {
            float ux = __shfl_up_sync(0xffffffffu, vb[j].x, 1);
            float uy = __shfl_up_sync(0xffffffffu, vb[j].y, 1);
            float dx = __shfl_down_sync(0xffffffffu, vb[j].x, 1);
            float dy = __shfl_down_sync(0xffffffffu, vb[j].y, 1);
            if (lane == 0 && L1) {
                const float* c = xb1 + (size_t)(b * 8 + 2 * j) * CH_STRIDE;
                ux = c[-1]; uy = c[CH_STRIDE - 1];
            }
            if (lane == 31 && R1) {
                const float* c = xb1 + (size_t)(b * 8 + 2 * j) * CH_STRIDE;
                dx = c[1]; dy = c[CH_STRIDE + 1];
            }
            float hx = vb[j].x, hy = vb[j].y;
            if (L1) { hx += ux; hy += uy; }
            if (R1) { hx += dx; hy += dy; }
            hB[j] = pk2(hx, hy);
            unsigned long long cen = pk2(vb[j].x, vb[j].y);
            ffma2(e2b, cen, cen);
        }

        __syncthreads();   // previous batch's vertical tile reads complete
#pragma unroll
        for (int j = 0; j < 4; j++) {
            *(unsigned long long*)(mb0 + 2 * j) = hA[j];
            *(unsigned long long*)(mb1 + 2 * j) = hB[j];
        }
        __syncthreads();   // hsum tile visible

        // prefetch next batch (v regs dead; 16-deep MLP)
        if (b < CC / 8 - 1) {
            const float* n0 = xb0 + (size_t)(b + 1) * 8 * CH_STRIDE;
            const float* n1 = xb1 + (size_t)(b + 1) * 8 * CH_STRIDE;
#pragma unroll
            for (int j = 0; j < 4; j++) {
                va[j].x = n0[(size_t)(2 * j)     * CH_STRIDE];
                va[j].y = n0[(size_t)(2 * j + 1) * CH_STRIDE];
                vb[j].x = n1[(size_t)(2 * j)     * CH_STRIDE];
                vb[j].y = n1[(size_t)(2 * j + 1) * CH_STRIDE];
            }
        }

        // ---- vertical pass + pooled + dots (latents shared by both pos) ----
        const unsigned long long ninth = pk2(1.f / 9.f, 1.f / 9.f);
#pragma unroll
        for (int j = 0; j < 4; j++) {
            const int off = 2 * j;
            unsigned long long sA = *(const unsigned long long*)(mb0 + off);
            if (U0) add2(sA, *(const unsigned long long*)(mb0 - WW * TILE_STRIDE + off));
            if (D0) add2(sA, *(const unsigned long long*)(mb0 + WW * TILE_STRIDE + off));
            unsigned long long sB = *(const unsigned long long*)(mb1 + off);
            if (U1) add2(sB, *(const unsigned long long*)(mb1 - WW * TILE_STRIDE + off));
            if (D1) add2(sB, *(const unsigned long long*)(mb1 + WW * TILE_STRIDE + off));
            unsigned long long pA = mul2(sA, ninth);
            unsigned long long pB = mul2(sB, ninth);
            ffma2(n2a, pA, pA);
            ffma2(n2b, pB, pB);

            float2 fA = upk2(pA);
            float2 fB = upk2(pB);
            unsigned long long a0 = pk2(fA.x, fA.x);
            unsigned long long a1 = pk2(fA.y, fA.y);
            unsigned long long b0 = pk2(fB.x, fB.x);
            unsigned long long b1 = pk2(fB.y, fB.y);
            const int c0 = b * 8 + 2 * j;
            const ulonglong2* l0 = (const ulonglong2*)(lbn_s + c0 * KK);
            // channel c0 (latents loaded once, feed both positions)
            {
                ulonglong2 q0 = l0[0], q1 = l0[1], q2 = l0[2], q3 = l0[3];
                ffma2(dotA[0], a0, q0.x); ffma2(dotA[1], a0, q0.y);
                ffma2(dotA[2], a0, q1.x); ffma2(dotA[3], a0, q1.y);
                ffma2(dotA[4], a0, q2.x); ffma2(dotA[5], a0, q2.y);
                ffma2(dotA[6], a0, q3.x); ffma2(dotA[7], a0, q3.y);
                ffma2(dotB[0], b0, q0.x); ffma2(dotB[1], b0, q0.y);
                ffma2(dotB[2], b0, q1.x); ffma2(dotB[3], b0, q1.y);
                ffma2(dotB[4], b0, q2.x); ffma2(dotB[5], b0, q2.y);
                ffma2(dotB[6], b0, q3.x); ffma2(dotB[7], b0, q3.y);
            }
            // channel c0+1
            {
                ulonglong2 q0 = l0[4], q1 = l0[5], q2 = l0[6], q3 = l0[7];
                ffma2(dotA[0], a1, q0.x); ffma2(dotA[1], a1, q0.y);
                ffma2(dotA[2], a1, q1.x); ffma2(dotA[3], a1, q1.y);
                ffma2(dotA[4], a1, q2.x); ffma2(dotA[5], a1, q2.y);
                ffma2(dotA[6], a1, q3.x); ffma2(dotA[7], a1, q3.y);
                ffma2(dotB[0], b1, q0.x); ffma2(dotB[1], b1, q0.y);
                ffma2(dotB[2], b1, q1.x); ffma2(dotB[3], b1, q1.y);
                ffma2(dotB[4], b1, q2.x); ffma2(dotB[5], b1, q2.y);
                ffma2(dotB[6], b1, q3.x); ffma2(dotB[7], b1, q3.y);
            }
        }
    }

    float2 t0 = upk2(e2a);
    float energyA = t0.x + t0.y;
    float2 t1 = upk2(e2b);
    float energyB = t1.x + t1.y;
    float2 t2 = upk2(n2a);
    float nA = t2.x + t2.y;
    float2 t3 = upk2(n2b);
    float nB = t3.x + t3.y;

    __syncthreads();

    // ---- energy max over block (max of both positions) ----
    float wm = warp_max(fmaxf(energyA, energyB));
    if (lane == 0) red_s[wid] = wm;
    __syncthreads();
    if (tid == 0) {
        float m = red_s[0];
        for (int w = 1; w < NWARP; w++) m = fmaxf(m, red_s[w]);
        s_emax = m;
    }
    __syncthreads();

    float denom = fmaxf(s_emax * (1.f / 256.f), EPSV);
    bool ambA = (energyA * (1.f / 256.f)) / denom > GATE;
    bool ambB = (energyB * (1.f / 256.f)) / denom > GATE;

    float cw = warp_sum((ambA ? 1.f : 0.f) + (ambB ? 1.f : 0.f));
    if (lane == 0) red_s[wid] = cw;
    __syncthreads();
    if (tid == 0) {
        float m = 0.f;
        for (int w = 0; w < NWARP; w++) m += red_s[w];
        s_cnt = m;
    }
    __syncthreads();
    if (s_cnt <= 0.f) { ambA = (energyA > 0.f); ambB = (energyB > 0.f); }

    // ---- logits -> softmax -> supp (registers, both positions) ----
    float dA[KK], dB[KK];
#pragma unroll
    for (int j = 0; j < 8; j++) {
        float2 ta = upk2(dotA[j]);
        dA[2 * j] = ta.x; dA[2 * j + 1] = ta.y;
        float2 tb = upk2(dotB[j]);
        dB[2 * j] = tb.x; dB[2 * j + 1] = tb.y;
    }
    float invA = 8.f / fmaxf(sqrtf(nA), 1e-12f);
    float invB = 8.f / fmaxf(sqrtf(nB), 1e-12f);
    float mxA = -1e30f, mxB = -1e30f;
#pragma unroll
    for (int k = 0; k < KK; k++) {
        dA[k] *= invA; mxA = fmaxf(mxA, dA[k]);
        dB[k] *= invB; mxB = fmaxf(mxB, dB[k]);
    }
    float seA = 0.f, seB = 0.f;
#pragma unroll
    for (int k = 0; k < KK; k++) {
        dA[k] = __expf(dA[k] - mxA); seA += dA[k];
        dB[k] = __expf(dB[k] - mxB); seB += dB[k];
    }
    float scA = (ambA ? 1.f : 0.f) / seA;
    float scB = (ambB ? 1.f : 0.f) / seB;

    float* supp_s = smem_pool;   // reuse (lbn/tile done)
#pragma unroll
    for (int k = 0; k < KK; k++) {
        supp_s[k * NPOS + p0] = dA[k] * scA;
        supp_s[k * NPOS + p1] = dB[k] * scB;
    }
    __syncthreads();

    // ---- per-k: colsum + exact top-88 presence (warps loop columns) ----
    for (int kk = wid; kk < KK; kk += NWARP) {
        float vals[22];
        float s = 0.f;
#pragma unroll
        for (int i = 0; i < 22; i++) {
            vals[i] = supp_s[kk * NPOS + lane + 32 * i];
            s += vals[i];
        }
        s = warp_sum(s);
        if (lane == 0) colsum_s[kk] = s;

        // binary search on nonneg float bit patterns for 88th largest
        unsigned V = 0u;
        for (int bit = 30; bit >= 0; --bit) {
            unsigned cand = V | (1u << bit);
            float cf = __uint_as_float(cand);
            int cnt = 0;
#pragma unroll
            for (int i = 0; i < 22; i++) cnt += (vals[i] >= cf) ? 1 : 0;
            cnt = __reduce_add_sync(0xffffffffu, cnt);
            if (cnt >= TOPK) V = cand;
        }
        float kth = __uint_as_float(V);
        int cgt = 0;
        float sgt = 0.f;
#pragma unroll
        for (int i = 0; i < 22; i++) {
            if (vals[i] > kth) { cgt++; sgt += vals[i]; }
        }
        cgt = __reduce_add_sync(0xffffffffu, cgt);
        sgt = warp_sum(sgt);
        if (lane == 0) {
            float pr = (sgt + kth * (float)(TOPK - cgt)) * (1.f / (float)TOPK);
            pres_out[n * (GG * KK) + g * KK + kk] = pr;
        }
    }
    __syncthreads();
    if (tid < KK) pinv_s[tid] = 1.f / fmaxf(colsum_s[tid], EPSV);
    __syncthreads();

    // ---- pw = supp / colsum -> global scratch ----
    float* gpw = g_pw + (size_t)(n * GG + g) * KK * NPOS;
#pragma unroll
    for (int k = 0; k < KK; k++) {
        gpw[k * NPOS + p0] = dA[k] * scA * pinv_s[k];
        gpw[k * NPOS + p1] = dB[k] * scB * pinv_s[k];
    }
}

// =====================================================================
// Kernel 2: partial tokens. CTA = (g, n, s); s splits positions in two
// 352-position halves. 128 threads, thread = channels (c, c+128).
// x staged through padded smem per 32-position chunk (coalesced LDG,
// conflict-free LDS); half-pw resident in smem (broadcast LDS128).
// 59.4KB dynamic smem -> 3 CTAs/SM, grid 512 -> ~1.15 waves.
// =====================================================================
#define NSPLIT 2
#define NPOS_H (NPOS / NSPLIT)        // 352
#define NPOS_H4 (NPOS_H / 4)          // 88
#define PCH 32                        // positions per chunk
#define NCHUNK_H (NPOS_H / PCH)       // 11
#define XS_STRIDE 36                  // floats per channel row (8 float4 + pad)
#define XS_FLOATS (CC * XS_STRIDE)    // 9216 floats = 36864 B
#define TOK_SMEM ((XS_FLOATS + KK * NPOS_H) * 4)   // 36864 + 22528 = 59392 B

__global__ void __launch_bounds__(128) k_tokens(const float* __restrict__ x) {
    extern __shared__ __align__(16) float dsm[];
    float* x_s  = dsm;                 // [256][36]
    float* pw_s = dsm + XS_FLOATS;     // [16][352]

    const int g = blockIdx.x, n = blockIdx.y, s = blockIdx.z;
    const int tid = threadIdx.x;
    const int pbase = s * NPOS_H;

    // load half-pw into smem (coalesced; first loop barrier orders it)
    {
        const float4* src = (const float4*)(g_pw + (size_t)(n * GG + g) * KK * NPOS);
        float4* dst = (float4*)pw_s;
#pragma unroll
        for (int it = 0; it < 11; it++) {
            int t = tid + 128 * it;          // 0..1407
            int k = t / NPOS_H4, j = t - k * NPOS_H4;
            dst[t] = src[k * NPOS4 + s * NPOS_H4 + j];
        }
    }

    const float* xg = x + (size_t)n * CC * CH_STRIDE + (size_t)g * NPOS + pbase;
    const int c0 = tid;
    const int c1 = tid + 128;

    unsigned long long accA[KK], accB[KK];
#pragma unroll
    for (int k = 0; k < KK; k++) { accA[k] = 0ULL; accB[k] = 0ULL; }

    for (int ch = 0; ch < NCHUNK_H; ch++) {
        const int p0 = ch * PCH;
        __syncthreads();   // prior chunk x_s reads done (and pw_s ready on ch=0)
        // stage 256 channels x 32 positions, coalesced LDG -> padded smem
#pragma unroll
        for (int it = 0; it < 16; it++) {
            int f = tid + 128 * it;          // 0..2047
            int c = f >> 3, i = f & 7;
            float4 vv = __ldg((const float4*)(xg + (size_t)c * CH_STRIDE + p0) + i);
            *(float4*)(x_s + c * XS_STRIDE + i * 4) = vv;
        }
        __syncthreads();

        const int p4base = ch * (PCH / 4);
#pragma unroll
        for (int i = 0; i < 8; i++) {
            float4 xa = *(const float4*)(x_s + c0 * XS_STRIDE + i * 4);
            float4 xb = *(const float4*)(x_s + c1 * XS_STRIDE + i * 4);
            unsigned long long alo = pk2(xa.x, xa.y);
            unsigned long long ahi = pk2(xa.z, xa.w);
            unsigned long long blo = pk2(xb.x, xb.y);
            unsigned long long bhi = pk2(xb.z, xb.w);
            const float* pwrow = pw_s + 4 * (p4base + i);
#pragma unroll
            for (int k = 0; k < KK; k++) {
                ulonglong2 pv = *(const ulonglong2*)(pwrow + k * NPOS_H);  // broadcast
                ffma2(accA[k], alo, pv.x);
                ffma2(accA[k], ahi, pv.y);
                ffma2(accB[k], blo, pv.x);
                ffma2(accB[k], bhi, pv.y);
            }
        }
    }

    float resA[KK], resB[KK];
#pragma unroll
    for (int k = 0; k < KK; k++) {
        float2 ta = upk2(accA[k]);
        resA[k] = ta.x + ta.y;
        float2 tb = upk2(accB[k]);
        resB[k] = tb.x + tb.y;
    }
    float* po = g_tok + (size_t)s * TOK_N;
    float4* oa = (float4*)(po + (size_t)(n * CC + c0) * (GG * KK) + g * KK);
    oa[0] = make_float4(resA[0], resA[1], resA[2], resA[3]);
    oa[1] = make_float4(resA[4], resA[5], resA[6], resA[7]);
    oa[2] = make_float4(resA[8], resA[9], resA[10], resA[11]);
    oa[3] = make_float4(resA[12], resA[13], resA[14], resA[15]);
    float4* ob = (float4*)(po + (size_t)(n * CC + c1) * (GG * KK) + g * KK);
    ob[0] = make_float4(resB[0], resB[1], resB[2], resB[3]);
    ob[1] = make_float4(resB[4], resB[5], resB[6], resB[7]);
    ob[2] = make_float4(resB[8], resB[9], resB[10], resB[11]);
    ob[3] = make_float4(resB[12], resB[13], resB[14], resB[15]);
}

// =====================================================================
// Kernel 3: finish. Blocks 0..255 sum the two token partials into out
// (fixed order -> deterministic); blocks 256..319 normalize presence.
// =====================================================================
__global__ void __launch_bounds__(256) k_finish(float* __restrict__ out) {
    const int b = blockIdx.x;
    if (b < 256) {
        const float4* p0 = (const float4*)g_tok;
        const float4* p1 = (const float4*)(g_tok + TOK_N);
        float4* o = (float4*)out;
        const int base = b * 1024 + threadIdx.x;
#pragma unroll
        for (int i = 0; i < 4; i++) {
            int idx = base + 256 * i;
            float4 a = p0[idx], c = p1[idx];
            o[idx] = make_float4(a.x + c.x, a.y + c.y, a.z + c.z, a.w + c.w);
        }
    } else {
        float* pres = out + TOK_N;
        const int n = b - 256;
        const int t = threadIdx.x;
        __shared__ float sh[2];
        float v = 0.f;
        if (t < 64) v = pres[n * 64 + t];
        float ws = warp_sum(v);
        if (t == 0) sh[0] = ws;
        if (t == 32) sh[1] = ws;
        __syncthreads();
        if (t < 64) pres[n * 64 + t] = v / fmaxf(sh[0] + sh[1], EPSV);
    }
}

extern "C" void kernel_launch(void* const* d_in, const int* in_sizes, int n_in,
                              void* d_out, int out_size) {
    const float* x = (const float*)d_in[0];
    const float* lb = (const float*)d_in[1];
    float* out = (float*)d_out;
    float* pres = out + (size_t)TOK_N;   // tokens first, then pres

    cudaFuncSetAttribute(k_tokens, cudaFuncAttributeMaxDynamicSharedMemorySize, TOK_SMEM);

    k_route<<<dim3(GG, NN), THR>>>(x, lb, pres);
    k_tokens<<<dim3(GG, NN, NSPLIT), 128, TOK_SMEM>>>(x);
    k_finish<<<320, 256>>>(out);
}